// round 6
// baseline (speedup 1.0000x reference)
#include <cuda_runtime.h>
#include <cuda_bf16.h>
#include <cstdint>

// Jones 4-pol congruence: V_p[a,d,n,t,f] = sum_{b,c} J[a,b,ant1[n],t,f] *
//                         V_m[b,c,n,t,f] * J[d,c,ant2[n],t,f]
// Layouts (row-major): V_m (2,2,NBL,T,F), jones (2,2,NANT,T,F), out (2,2,NBL,T,F)
// R2: L2 hints -> 1.03 GB compulsory traffic.  R4 (prev best, 155.5us): 12-deep
// register-batched LDG. R5 (FAILED): 24-deep cost too many warps.
// R6: cp.async pipeline — V_m streamed via cp.async.cg (+L2::evict_first) into a
//     3-slot smem ring, 3 stages in flight per thread with ZERO register payload;
//     Jones via __ldg (L2-resident). Thread-private ring -> no block syncs.

#define NPOL   2
#define NANT   64
#define NBL    2016
#define NTIMES 64
#define NFREQS 256

#define TF      (NTIMES * NFREQS)   // 16384 elems per (bl|ant) per plane
#define SPLANE  (NBL * TF)          // 33,030,144  (V_m / out plane stride)
#define SJPLANE (NANT * TF)         // 1,048,576   (jones plane stride)

#define STAGES  8                   // stages per CTA
#define RING    3                   // smem ring slots (3 stages in flight)
#define THREADS 256
// per CTA: STAGES*THREADS float4 groups = 2048 -> 2 CTAs per baseline (TF/4 = 4096)
#define CTAS_PER_BL 2
#define NCTAS   (NBL * CTAS_PER_BL) // 4032
#define STAGE_F 1024                // floats per plane per stage (256 thr * 4)

__device__ __forceinline__ void stcs4(float* p, float4 v) {
    __stcs((float4*)p, v);
}

__global__ __launch_bounds__(THREADS, 3) void jones_congruence_kernel(
    const float* __restrict__ Vm,
    const float* __restrict__ J,
    const int*   __restrict__ ant1,
    const int*   __restrict__ ant2,
    float*       __restrict__ out)
{
    __shared__ float4 buf[RING][4][THREADS];   // 48 KB

    const int t   = threadIdx.x;
    const int cta = blockIdx.x;
    const int n   = cta >> 1;                        // baseline
    const int cta_tf = (cta & 1) * (TF / 2) + 4 * t; // this thread's base offset

    const int a1 = __ldg(&ant1[n]);
    const int a2 = __ldg(&ant2[n]);

    const float* vb  = Vm  + n  * TF + cta_tf;
    const float* j1b = J   + a1 * TF + cta_tf;
    const float* j2b = J   + a2 * TF + cta_tf;
    float*       ob  = out + n  * TF + cta_tf;

    // L2 evict-first policy for the stream-once V_m fetches
    uint64_t pol;
    asm volatile("createpolicy.fractional.L2::evict_first.b64 %0, 1.0;" : "=l"(pol));

    // Issue one stage of V_m (4 planes x 16B per thread) into ring slot s%RING
#define ISSUE_STAGE(s)                                                        \
    {                                                                         \
        _Pragma("unroll")                                                     \
        for (int p = 0; p < 4; p++) {                                         \
            unsigned dst = (unsigned)__cvta_generic_to_shared(                \
                &buf[(s) % RING][p][t]);                                      \
            const float* src = vb + p * SPLANE + (s) * STAGE_F;               \
            asm volatile(                                                     \
                "cp.async.cg.shared.global.L2::cache_hint [%0], [%1], 16, %2;"\
                :: "r"(dst), "l"(src), "l"(pol) : "memory");                  \
        }                                                                     \
        asm volatile("cp.async.commit_group;" ::: "memory");                  \
    }

    // prologue: 3 stages in flight
    ISSUE_STAGE(0)
    ISSUE_STAGE(1)
    ISSUE_STAGE(2)

#pragma unroll
    for (int s = 0; s < STAGES; s++) {
        // Jones for this stage (L2 hits; latency covered by other warps)
        float4 A0 = __ldg((const float4*)(j1b + 0 * SJPLANE + s * STAGE_F));
        float4 A1 = __ldg((const float4*)(j1b + 1 * SJPLANE + s * STAGE_F));
        float4 A2 = __ldg((const float4*)(j1b + 2 * SJPLANE + s * STAGE_F));
        float4 A3 = __ldg((const float4*)(j1b + 3 * SJPLANE + s * STAGE_F));
        float4 B0 = __ldg((const float4*)(j2b + 0 * SJPLANE + s * STAGE_F));
        float4 B1 = __ldg((const float4*)(j2b + 1 * SJPLANE + s * STAGE_F));
        float4 B2 = __ldg((const float4*)(j2b + 2 * SJPLANE + s * STAGE_F));
        float4 B3 = __ldg((const float4*)(j2b + 3 * SJPLANE + s * STAGE_F));

        // wait until stage s's V_m has landed (always exactly 3 groups
        // outstanding thanks to the tail's empty commit_groups)
        asm volatile("cp.async.wait_group 2;" ::: "memory");

        const int slot = s % RING;
        float4 v00 = buf[slot][0][t];
        float4 v01 = buf[slot][1][t];
        float4 v10 = buf[slot][2][t];
        float4 v11 = buf[slot][3][t];

        float4 o00, o01, o10, o11;
        // M = J1 @ V ; O[a][d] = sum_c M[a][c] * J2[d][c]  (real -> conj = id)
#define JONES_LANE(c)                                                   \
        {                                                               \
            float m00 = A0.c * v00.c + A1.c * v10.c;                    \
            float m01 = A0.c * v01.c + A1.c * v11.c;                    \
            float m10 = A2.c * v00.c + A3.c * v10.c;                    \
            float m11 = A2.c * v01.c + A3.c * v11.c;                    \
            o00.c = m00 * B0.c + m01 * B1.c;                            \
            o01.c = m00 * B2.c + m01 * B3.c;                            \
            o10.c = m10 * B0.c + m11 * B1.c;                            \
            o11.c = m10 * B2.c + m11 * B3.c;                            \
        }
        JONES_LANE(x)
        JONES_LANE(y)
        JONES_LANE(z)
        JONES_LANE(w)
#undef JONES_LANE

        stcs4(ob + 0 * SPLANE + s * STAGE_F, o00);
        stcs4(ob + 1 * SPLANE + s * STAGE_F, o01);
        stcs4(ob + 2 * SPLANE + s * STAGE_F, o10);
        stcs4(ob + 3 * SPLANE + s * STAGE_F, o11);

        // refill the ring (slot s%RING is fully consumed above); at the tail,
        // commit empty groups so wait_group 2 keeps exact semantics
        if (s + RING < STAGES) {
            ISSUE_STAGE(s + RING)
        } else {
            asm volatile("cp.async.commit_group;" ::: "memory");
        }
    }
#undef ISSUE_STAGE
}

extern "C" void kernel_launch(void* const* d_in, const int* in_sizes, int n_in,
                              void* d_out, int out_size)
{
    const float* Vm   = (const float*)d_in[0];
    const float* J    = (const float*)d_in[1];
    const int*   ant1 = (const int*)d_in[2];
    const int*   ant2 = (const int*)d_in[3];
    float*       out  = (float*)d_out;

    jones_congruence_kernel<<<NCTAS, THREADS>>>(Vm, J, ant1, ant2, out);
}